// round 1
// baseline (speedup 1.0000x reference)
#include <cuda_runtime.h>

// Problem constants
#define GRID   128
#define BLOCK  256
#define Bsz    256
#define Tsz    512
#define Hsz    512
#define NPOS   128
#define NACT   64
#define Isz    192          // NPOS + NACT
#define Ktot   704          // Isz + Hsz
#define KT     32           // K-tile
#define NTILES 22           // 704/32
#define XTILES 6            // tiles 0..5 come from x, 6..21 from h

// h ping-pong buffers, layout [H][B] (unit-major) so step loads are coalesced copies
__device__ float g_h[2][Hsz * Bsz];
__device__ volatile unsigned g_bar;

__global__ void reset_kernel() { g_bar = 0u; }

__device__ __forceinline__ float sigf(float x) { return 1.0f / (1.0f + __expf(-x)); }

__device__ __forceinline__ void load_tile(float4* pre, int kt, int t,
                                          const float* __restrict__ obs,
                                          const float* __restrict__ act,
                                          const float* __restrict__ hread,
                                          bool h_gather, int tid)
{
    if (kt < 4) {                       // obs: thread owns batch=tid, 32 contiguous k
        const float4* src = (const float4*)(obs + ((size_t)tid * Tsz + t) * NPOS + kt * KT);
#pragma unroll
        for (int r = 0; r < 8; ++r) pre[r] = src[r];
    } else if (kt < XTILES) {           // act
        const float4* src = (const float4*)(act + ((size_t)tid * Tsz + t) * NACT + (kt - 4) * KT);
#pragma unroll
        for (int r = 0; r < 8; ++r) pre[r] = src[r];
    } else if (h_gather) {              // t==0: h0 is [B][H], gather per batch
        const float4* src = (const float4*)(hread + (size_t)tid * Hsz + (kt - XTILES) * KT);
#pragma unroll
        for (int r = 0; r < 8; ++r) pre[r] = src[r];
    } else {                            // h buffer [H][B]: straight block copy, L2-coherent loads
        const float4* src = (const float4*)(hread + (size_t)(kt - XTILES) * KT * Bsz);
#pragma unroll
        for (int r = 0; r < 8; ++r) pre[r] = __ldcg(src + tid + BLOCK * r);
    }
}

__device__ __forceinline__ void store_tile(const float4* pre, int kt, bool h_gather,
                                           float* Zt, int tid)
{
    bool gathered = (kt < XTILES) || h_gather;
    if (gathered) {                     // transpose: pre[r] holds 4 consecutive k for batch=tid
#pragma unroll
        for (int r = 0; r < 8; ++r) {
            Zt[(r * 4 + 0) * Bsz + tid] = pre[r].x;
            Zt[(r * 4 + 1) * Bsz + tid] = pre[r].y;
            Zt[(r * 4 + 2) * Bsz + tid] = pre[r].z;
            Zt[(r * 4 + 3) * Bsz + tid] = pre[r].w;
        }
    } else {                            // already [k][b]: vector copy
        float4* dst = (float4*)Zt;
#pragma unroll
        for (int r = 0; r < 8; ++r) dst[tid + BLOCK * r] = pre[r];
    }
}

__global__ void __launch_bounds__(BLOCK, 1) lstm_kernel(
    const float* __restrict__ obs, const float* __restrict__ act,
    const float* __restrict__ h0,  const float* __restrict__ c0,
    const float* __restrict__ W_ih, const float* __restrict__ W_hh,
    const float* __restrict__ b_ih, const float* __restrict__ b_hh,
    const float* __restrict__ W_out, const float* __restrict__ b_out,
    float* __restrict__ out)
{
    extern __shared__ float sm[];
    float* Wsm  = sm;                       // [704][16]  (k-major; 16 = unit*4 + gate)
    float* Zt   = Wsm + Ktot * 16;          // [32][256]  current K-tile of [x_t | h]
    float* csm  = Zt + KT * Bsz;            // [4][256]   cell state for my 4 units
    float* wout = csm + 4 * Bsz;            // [512]
    float* bsm  = wout + Hsz;               // [16]       b_ih + b_hh for my 16 gate rows
    float* red  = bsm + 16;                 // [8]        reduction scratch

    const int tid = threadIdx.x;
    const int cta = blockIdx.x;
    const int u   = tid >> 6;               // unit within CTA (0..3)
    const int b0  = (tid & 63) << 2;        // batch base (0..252, step 4)
    const int j   = cta * 4 + u;            // global hidden unit

    // ---- one-time init ----
    for (int idx = tid; idx < Ktot * 16; idx += BLOCK) {
        int k = idx >> 4, col = idx & 15;
        int uu = col >> 2, g = col & 3;
        int row = g * Hsz + cta * 4 + uu;
        Wsm[idx] = (k < Isz) ? W_ih[(size_t)row * Isz + k]
                             : W_hh[(size_t)row * Hsz + (k - Isz)];
    }
    for (int idx = tid; idx < 4 * Bsz; idx += BLOCK) {
        int uu = idx >> 8, b = idx & 255;
        csm[idx] = c0[(size_t)b * Hsz + cta * 4 + uu];
    }
    for (int idx = tid; idx < Hsz; idx += BLOCK) wout[idx] = W_out[idx];
    if (tid < 16) {
        int uu = tid >> 2, g = tid & 3;
        int row = g * Hsz + cta * 4 + uu;
        bsm[tid] = b_ih[row] + b_hh[row];
    }
    __syncthreads();

    float bi[4];
#pragma unroll
    for (int g = 0; g < 4; ++g) bi[g] = bsm[u * 4 + g];

    const float bout = b_out[0];
    unsigned barTarget = GRID;
    float4 pre[8];

    for (int t = 0; t < Tsz; ++t) {
        const bool  hg     = (t == 0);
        const float* hread = hg ? h0 : g_h[(t - 1) & 1];
        float*       hwrite = g_h[t & 1];

        float acc[4][4];
#pragma unroll
        for (int bb = 0; bb < 4; ++bb)
#pragma unroll
            for (int g = 0; g < 4; ++g) acc[bb][g] = bi[g];

        load_tile(pre, 0, t, obs, act, hread, hg, tid);

        for (int kt = 0; kt < NTILES; ++kt) {
            __syncthreads();                        // Zt free (prev compute done)
            store_tile(pre, kt, hg, Zt, tid);
            __syncthreads();                        // tile visible
            if (kt + 1 < NTILES) load_tile(pre, kt + 1, t, obs, act, hread, hg, tid);

            const float* wp = Wsm + (size_t)kt * KT * 16 + u * 4;
#pragma unroll
            for (int k = 0; k < KT; ++k) {
                float4 wv = *(const float4*)(wp + k * 16);          // broadcast
                float4 zb = *(const float4*)(Zt + k * Bsz + b0);    // 4 batches
                acc[0][0] += zb.x * wv.x; acc[0][1] += zb.x * wv.y;
                acc[0][2] += zb.x * wv.z; acc[0][3] += zb.x * wv.w;
                acc[1][0] += zb.y * wv.x; acc[1][1] += zb.y * wv.y;
                acc[1][2] += zb.y * wv.z; acc[1][3] += zb.y * wv.w;
                acc[2][0] += zb.z * wv.x; acc[2][1] += zb.z * wv.y;
                acc[2][2] += zb.z * wv.z; acc[2][3] += zb.z * wv.w;
                acc[3][0] += zb.w * wv.x; acc[3][1] += zb.w * wv.y;
                acc[3][2] += zb.w * wv.z; acc[3][3] += zb.w * wv.w;
            }
        }

        // ---- elementwise LSTM cell update (all in registers + smem c) ----
        float hn[4];
#pragma unroll
        for (int bb = 0; bb < 4; ++bb) {
            float iv = sigf(acc[bb][0]);
            float fv = sigf(acc[bb][1]);
            float gv = tanhf(acc[bb][2]);
            float ov = sigf(acc[bb][3]);
            float cold = csm[u * Bsz + b0 + bb];
            float cn = fv * cold + iv * gv;
            csm[u * Bsz + b0 + bb] = cn;
            hn[bb] = ov * tanhf(cn);
        }
        *(float4*)(hwrite + (size_t)j * Bsz + b0) = make_float4(hn[0], hn[1], hn[2], hn[3]);

        // ---- grid-wide barrier (release/acquire) ----
        __syncthreads();
        if (tid == 0) {
            __threadfence();
            atomicAdd((unsigned*)&g_bar, 1u);
            while (g_bar < barTarget) { }
            __threadfence();
        }
        __syncthreads();
        barTarget += GRID;

        // ---- readout for this step: CTA c owns batches 2c, 2c+1 ----
        {
            const float* hc = hwrite;   // complete after barrier
#pragma unroll
            for (int bb = 0; bb < 2; ++bb) {
                int b = cta * 2 + bb;
                float p = __ldcg(hc + (size_t)tid * Bsz + b) * wout[tid]
                        + __ldcg(hc + ((size_t)tid + 256) * Bsz + b) * wout[tid + 256];
#pragma unroll
                for (int off = 16; off; off >>= 1)
                    p += __shfl_down_sync(0xffffffffu, p, off);
                if ((tid & 31) == 0) red[tid >> 5] = p;
                __syncthreads();
                if (tid == 0) {
                    float s = red[0] + red[1] + red[2] + red[3]
                            + red[4] + red[5] + red[6] + red[7] + bout;
                    out[(size_t)b * Tsz + t] = s;
                }
                __syncthreads();
            }
        }
    }
}

extern "C" void kernel_launch(void* const* d_in, const int* in_sizes, int n_in,
                              void* d_out, int out_size)
{
    (void)in_sizes; (void)n_in; (void)out_size;
    const size_t smem_bytes =
        (size_t)(Ktot * 16 + KT * Bsz + 4 * Bsz + Hsz + 16 + 8) * sizeof(float); // ~84 KB
    cudaFuncSetAttribute(lstm_kernel, cudaFuncAttributeMaxDynamicSharedMemorySize,
                         (int)smem_bytes);

    reset_kernel<<<1, 1>>>();
    lstm_kernel<<<GRID, BLOCK, smem_bytes>>>(
        (const float*)d_in[0],  // observation
        (const float*)d_in[1],  // action
        (const float*)d_in[2],  // h0
        (const float*)d_in[3],  // c0
        (const float*)d_in[4],  // W_ih
        (const float*)d_in[5],  // W_hh
        (const float*)d_in[6],  // b_ih
        (const float*)d_in[7],  // b_hh
        (const float*)d_in[8],  // W_out
        (const float*)d_in[9],  // b_out
        (float*)d_out);
}